// round 3
// baseline (speedup 1.0000x reference)
#include <cuda_runtime.h>
#include <stdint.h>

// Scratch: static __device__ arrays (no allocation allowed in kernel_launch).
#define MAXN (1 << 17)
__device__ float4 g_pack[MAXN];   // (x, y, z, r) per point
__device__ int    g_hash[MAXN];   // spatial hash per point

__device__ __forceinline__ int voxel_hash(int cx, int cy, int cz) {
    // int32 wraparound semantics identical to jnp int32 sum; use unsigned to avoid UB.
    return (int)((unsigned)cx * 73856093u +
                 (unsigned)cy * 19349663u +
                 (unsigned)cz * 83492791u);
}

__global__ void pack_kernel(const float* __restrict__ pts,
                            const float* __restrict__ rad,
                            int n) {
    int j = blockIdx.x * blockDim.x + threadIdx.x;
    if (j >= n || j >= MAXN) return;
    float x = pts[3 * j + 0];
    float y = pts[3 * j + 1];
    float z = pts[3 * j + 2];
    float r = rad[j];
    g_pack[j] = make_float4(x, y, z, r);
    // VOXEL_SIZE = 1.0 -> division exact; astype(int32) truncates toward zero, points >= 0.
    g_hash[j] = voxel_hash((int)x, (int)y, (int)z);
}

__global__ __launch_bounds__(256)
void edge_kernel(const int* __restrict__ d_start,
                 float* __restrict__ out,
                 int n) {
    __shared__ int sh[27];

    const int start = d_start[0];
    const int i = start + blockIdx.y;          // global row index
    const float4 pi = g_pack[i];               // broadcast load (L1 hit)
    const float ri = pi.w;
    const bool row_on = (ri < 1.0f);           // DIS_THRESHOLD

    if (threadIdx.x < 27) {
        int t = threadIdx.x;
        int ox = t / 9 - 1;
        int oy = (t / 3) % 3 - 1;
        int oz = t % 3 - 1;
        sh[t] = voxel_hash((int)pi.x + ox, (int)pi.y + oy, (int)pi.z + oz);
    }
    __syncthreads();

    const int j0 = blockIdx.x * (256 * 4) + threadIdx.x * 4;
    if (j0 >= n) return;

    float4 o;
    float* op = reinterpret_cast<float*>(&o);

#pragma unroll
    for (int k = 0; k < 4; k++) {
        const int j = j0 + k;
        float v = 0.0f;
        if (j < n) {
            const float4 pj = g_pack[j];
            const float dx = pi.x - pj.x;
            const float dy = pi.y - pj.y;
            const float dz = pi.z - pj.z;
            const float d2 = dx * dx + dy * dy + dz * dz;
            const float rj = pj.w;
            const float mr = 1.5f * fminf(ri, rj);
            const float s  = fminf(ri, mr) + fminf(rj, mr);
            // Rare slow path: only genuinely-near pairs check the 27 neighbor hashes.
            if (row_on && (j > i) && (d2 < s * s)) {
                const int h = g_hash[j];
                bool m = false;
#pragma unroll
                for (int t = 0; t < 27; t++) m |= (h == sh[t]);
                if (m) v = d2;
            }
        }
        op[k] = v;
    }

    const size_t off = (size_t)blockIdx.y * (size_t)n + (size_t)j0;
    if (j0 + 4 <= n) {
        *reinterpret_cast<float4*>(out + off) = o;   // 16B-aligned: j0 % 4 == 0
    } else {
        for (int k = 0; k < 4 && j0 + k < n; k++) out[off + k] = op[k];
    }
}

extern "C" void kernel_launch(void* const* d_in, const int* in_sizes, int n_in,
                              void* d_out, int out_size) {
    const float* pts   = (const float*)d_in[0];
    const float* rad   = (const float*)d_in[1];
    const int*   start = (const int*)d_in[2];
    float* out = (float*)d_out;

    const int n = in_sizes[0] / 3;           // number of points
    const int chunk = out_size / n;          // rows (end_idx - start_idx)

    pack_kernel<<<(n + 255) / 256, 256>>>(pts, rad, n);

    dim3 grid((n + 1023) / 1024, chunk);
    edge_kernel<<<grid, 256>>>(start, out, n);
}

// round 4
// speedup vs baseline: 1.8668x; 1.8668x over previous
#include <cuda_runtime.h>
#include <stdint.h>

// Scratch: static __device__ arrays (no allocation allowed in kernel_launch).
#define MAXN (1 << 17)
__device__ float4 g_pack[MAXN];   // (x, y, z, r) per point

__global__ void pack_kernel(const float* __restrict__ pts,
                            const float* __restrict__ rad,
                            int n) {
    int j = blockIdx.x * blockDim.x + threadIdx.x;
    if (j >= n || j >= MAXN) return;
    float x = pts[3 * j + 0];
    float y = pts[3 * j + 1];
    float z = pts[3 * j + 2];
    float r = rad[j];
    g_pack[j] = make_float4(x, y, z, r);
}

// Each block: 1024-column j-tile x 8 rows.
// j mapping is strided (tid + k*256) so every g_pack load is a fully
// coalesced LDG.128; pj stays in registers across the 8 rows.
//
// Hash check dropped: s <= ri+rj <= 0.7, so d2 < s*s implies per-axis
// |dx| < 1 implies voxel delta in {-1,0,1} implies the 27-neighborhood
// hash match is always true; collisions only affect pairs that fail the
// distance test (output 0 either way). Boolean-exact equivalence.
#define ROWS_PER_BLK 8
#define JPT 4   // j's per thread

__global__ __launch_bounds__(256)
void edge_kernel(const int* __restrict__ d_start,
                 float* __restrict__ out,
                 int n, int chunk) {
    const int tid = threadIdx.x;
    const int jbase = blockIdx.x * (256 * JPT);

    int   jj[JPT];
    float px[JPT], py[JPT], pz[JPT], pr[JPT];
    bool  jv[JPT];

#pragma unroll
    for (int k = 0; k < JPT; k++) {
        int j = jbase + k * 256 + tid;
        jj[k] = j;
        jv[k] = (j < n);
        float4 pj = jv[k] ? g_pack[j] : make_float4(0.f, 0.f, 0.f, 0.f);
        px[k] = pj.x; py[k] = pj.y; pz[k] = pj.z; pr[k] = pj.w;
    }

    const int start = d_start[0];
    const int row0 = blockIdx.y * ROWS_PER_BLK;

#pragma unroll
    for (int r = 0; r < ROWS_PER_BLK; r++) {
        const int row = row0 + r;
        if (row >= chunk) return;
        const int i = start + row;
        const float4 pi = g_pack[i];          // uniform broadcast, L1 hit
        const float ri = pi.w;
        const bool row_on = (ri < 1.0f);      // DIS_THRESHOLD
        const size_t base = (size_t)row * (size_t)n;

#pragma unroll
        for (int k = 0; k < JPT; k++) {
            const float dx = pi.x - px[k];
            const float dy = pi.y - py[k];
            const float dz = pi.z - pz[k];
            const float d2 = dx * dx + dy * dy + dz * dz;
            const float rj = pr[k];
            const float mr = 1.5f * fminf(ri, rj);
            const float s  = fminf(ri, mr) + fminf(rj, mr);
            const bool ok = row_on && (jj[k] > i) && (d2 < s * s);
            const float v = ok ? d2 : 0.0f;
            if (jv[k]) out[base + jj[k]] = v;   // coalesced 128B per warp
        }
    }
}

extern "C" void kernel_launch(void* const* d_in, const int* in_sizes, int n_in,
                              void* d_out, int out_size) {
    const float* pts   = (const float*)d_in[0];
    const float* rad   = (const float*)d_in[1];
    const int*   start = (const int*)d_in[2];
    float* out = (float*)d_out;

    const int n = in_sizes[0] / 3;           // number of points
    const int chunk = out_size / n;          // rows (end_idx - start_idx)

    pack_kernel<<<(n + 255) / 256, 256>>>(pts, rad, n);

    dim3 grid((n + 1023) / 1024, (chunk + ROWS_PER_BLK - 1) / ROWS_PER_BLK);
    edge_kernel<<<grid, 256>>>(start, out, n, chunk);
}

// round 6
// speedup vs baseline: 4.6223x; 2.4760x over previous
#include <cuda_runtime.h>
#include <stdint.h>

// Scratch: static __device__ arrays (no allocation allowed in kernel_launch).
#define MAXN (1 << 17)
__device__ float4 g_pack[MAXN];   // (x, y, z, r) per point

__global__ void pack_kernel(const float* __restrict__ pts,
                            const float* __restrict__ rad,
                            int n) {
    int j = blockIdx.x * blockDim.x + threadIdx.x;
    if (j >= n || j >= MAXN) return;
    g_pack[j] = make_float4(pts[3 * j + 0], pts[3 * j + 1], pts[3 * j + 2], rad[j]);
}

// ---- packed f32x2 helpers (sm_103a; only reachable via explicit PTX) ----
__device__ __forceinline__ unsigned long long pack2(float lo, float hi) {
    unsigned long long r;
    asm("mov.b64 %0, {%1, %2};" : "=l"(r) : "f"(lo), "f"(hi));
    return r;
}
__device__ __forceinline__ void unpack2(unsigned long long v, float& lo, float& hi) {
    asm("mov.b64 {%0, %1}, %2;" : "=f"(lo), "=f"(hi) : "l"(v));
}
__device__ __forceinline__ unsigned long long add2(unsigned long long a, unsigned long long b) {
    unsigned long long r;
    asm("add.rn.f32x2 %0, %1, %2;" : "=l"(r) : "l"(a), "l"(b));
    return r;
}
__device__ __forceinline__ unsigned long long mul2(unsigned long long a, unsigned long long b) {
    unsigned long long r;
    asm("mul.rn.f32x2 %0, %1, %2;" : "=l"(r) : "l"(a), "l"(b));
    return r;
}
__device__ __forceinline__ unsigned long long fma2(unsigned long long a, unsigned long long b,
                                                   unsigned long long c) {
    unsigned long long r;
    asm("fma.rn.f32x2 %0, %1, %2, %3;" : "=l"(r) : "l"(a), "l"(b), "l"(c));
    return r;
}

// Exact-equivalence notes:
//  * hash mask dropped: s <= ri+rj < 0.7, so d2 < s*s forces per-axis |d| < 1
//    -> voxel delta in {-1,0,1} -> the 27-neighborhood hash test is always true
//    for every pair that can be valid; collisions only touch pairs whose output
//    is 0 either way. Boolean-exact.
//  * fast-path filter: s*s < 0.49 always (radii in [0.05, 0.35)), so if every
//    d2 in a thread's 4 elements is >= 0.49, all 4 outputs are exactly 0.
//    Conservative -> boolean-exact; the full reference predicate (j>i, ri<1,
//    d2 < s*s with the reference min/min/add order) runs in the rare slow path.
#define ROWS 8
#define JPT  4   // j's per thread, strided by 256 for coalescing

__global__ __launch_bounds__(256)
void edge_kernel(const int* __restrict__ d_start,
                 float* __restrict__ out,
                 int n, int chunk) {
    const int tid = threadIdx.x;
    const int jbase = blockIdx.x * (256 * JPT);

    // Tile setup: load 4 float4s (coalesced LDG.128), pre-pack negated coords.
    float pr[JPT];
    bool  jv[JPT];
    float nx[JPT], ny[JPT], nz[JPT];
#pragma unroll
    for (int k = 0; k < JPT; k++) {
        const int j = jbase + k * 256 + tid;
        jv[k] = (j < n);
        float4 pj = jv[k] ? g_pack[j] : make_float4(1e30f, 1e30f, 1e30f, 1e30f);
        nx[k] = -pj.x; ny[k] = -pj.y; nz[k] = -pj.z; pr[k] = pj.w;
    }
    unsigned long long npx[2], npy[2], npz[2];
#pragma unroll
    for (int p = 0; p < 2; p++) {
        npx[p] = pack2(nx[2 * p], nx[2 * p + 1]);
        npy[p] = pack2(ny[2 * p], ny[2 * p + 1]);
        npz[p] = pack2(nz[2 * p], nz[2 * p + 1]);
    }

    const int start = d_start[0];
    const int row0 = blockIdx.y * ROWS;
    float* op = out + (size_t)row0 * (size_t)n + (size_t)(jbase + tid);

#pragma unroll
    for (int r = 0; r < ROWS; r++, op += n) {
        const int row = row0 + r;
        if (row >= chunk) return;
        const int i = start + row;
        const float4 pi = g_pack[i];           // uniform broadcast, L1 hit

        const unsigned long long pix = pack2(pi.x, pi.x);
        const unsigned long long piy = pack2(pi.y, pi.y);
        const unsigned long long piz = pack2(pi.z, pi.z);

        float d2s[JPT];
#pragma unroll
        for (int p = 0; p < 2; p++) {
            unsigned long long dx = add2(pix, npx[p]);   // pi - pj (exact: x + (-y))
            unsigned long long dy = add2(piy, npy[p]);
            unsigned long long dz = add2(piz, npz[p]);
            unsigned long long t  = mul2(dx, dx);
            t = fma2(dy, dy, t);
            t = fma2(dz, dz, t);
            unpack2(t, d2s[2 * p], d2s[2 * p + 1]);
        }

        const float mn = fminf(fminf(d2s[0], d2s[1]), fminf(d2s[2], d2s[3]));
        if (mn < 0.49f) {
            // Rare slow path: full reference predicate.
            const float ri = pi.w;
            const bool row_on = (ri < 1.0f);   // DIS_THRESHOLD
#pragma unroll
            for (int k = 0; k < JPT; k++) {
                const int j = jbase + k * 256 + tid;
                const float rj = pr[k];
                const float mr = 1.5f * fminf(ri, rj);
                const float s  = fminf(ri, mr) + fminf(rj, mr);
                const bool ok = row_on && (j > i) && (d2s[k] < s * s);
                if (jv[k]) op[k * 256] = ok ? d2s[k] : 0.0f;
            }
        } else {
            // Fast path: everything in this thread's 4 elements is zero.
#pragma unroll
            for (int k = 0; k < JPT; k++)
                if (jv[k]) op[k * 256] = 0.0f;
        }
    }
}

extern "C" void kernel_launch(void* const* d_in, const int* in_sizes, int n_in,
                              void* d_out, int out_size) {
    const float* pts   = (const float*)d_in[0];
    const float* rad   = (const float*)d_in[1];
    const int*   start = (const int*)d_in[2];
    float* out = (float*)d_out;

    const int n = in_sizes[0] / 3;           // number of points
    const int chunk = out_size / n;          // rows (end_idx - start_idx)

    pack_kernel<<<(n + 255) / 256, 256>>>(pts, rad, n);

    dim3 grid((n + 256 * JPT - 1) / (256 * JPT), (chunk + ROWS - 1) / ROWS);
    edge_kernel<<<grid, 256>>>(start, out, n, chunk);
}